// round 11
// baseline (speedup 1.0000x reference)
#include <cuda_runtime.h>
#include <cuda_fp16.h>
#include <math.h>
#include <stdint.h>

// ---------------------------------------------------------------------------
// DeepseekV2 MLA forward, B=1 S=2048 HID=2048 H=16 NOPE=128 ROPE=64 VD=128.
// Round 11: R10 with the PV stride bug fixed (sC must be VD so each head's
// fp16 ctx lands at its own column block; R10 passed 0 -> all heads aliased).
//  (a) GEMM: 128 threads / 4 warps / 64x64 warp tiles -> mma:ldmatrix 32:8.
//  (b) QK skipped blocks write the attn fp32 zeros; softmax writes only the
//      banded fp32 region.
// ---------------------------------------------------------------------------

#define S_LEN 2048
#define HID   2048
#define HEADS 16
#define NOPE  128
#define ROPE  64
#define VD    128
#define QD    192
#define QLR   1536
#define KVLR  512
#define KVD_W (KVLR + 64)            // 576
#define QUP_N (HEADS * QD)           // 3072
#define KUP_N (HEADS * (NOPE + VD))  // 4096
#define WKD_PAD 640

// ---------------- fp32 scratch ----------------
#define F_QRAW 0L
#define F_QBUF (F_QRAW + (long)S_LEN * QLR)
#define F_KVD  (F_QBUF + (long)S_LEN * QUP_N)
#define F_KV   (F_KVD  + (long)S_LEN * KVD_W)
#define F_TOT  (F_KV   + (long)S_LEN * KUP_N)

// ---------------- fp16 scratch ----------------
#define O_HID  0L
#define O_WQD  (O_HID  + (long)S_LEN * HID)
#define O_WQU  (O_WQD  + (long)QLR * HID)
#define O_WKD  (O_WQU  + (long)QUP_N * QLR)
#define O_WKU  (O_WKD  + (long)WKD_PAD * HID)
#define O_WO   (O_WKU  + (long)KUP_N * KVLR)
#define O_QRN  (O_WO   + (long)HID * (HEADS * VD))
#define O_KVN  (O_QRN  + (long)S_LEN * QLR)
#define O_QALL (O_KVN  + (long)S_LEN * KVLR)
#define O_KALL (O_QALL + (long)HEADS * S_LEN * QD)
#define O_KV16 (O_KALL + (long)HEADS * S_LEN * QD)
#define O_ATTN (O_KV16 + (long)S_LEN * KUP_N)
#define O_CTX  (O_ATTN + (long)HEADS * S_LEN * S_LEN)
#define O_TOT  (O_CTX  + (long)S_LEN * HID)

__device__ __align__(256) float  g_f32[F_TOT];
__device__ __align__(256) __half g_h16[O_TOT];

// ---------------------------------------------------------------------------
__device__ __forceinline__ unsigned smem_u32(const void* p) {
    return (unsigned)__cvta_generic_to_shared(p);
}
__device__ __forceinline__ void ldm_x4(uint32_t r[4], unsigned addr) {
    asm volatile("ldmatrix.sync.aligned.m8n8.x4.shared.b16 {%0,%1,%2,%3}, [%4];"
                 : "=r"(r[0]), "=r"(r[1]), "=r"(r[2]), "=r"(r[3]) : "r"(addr));
}
__device__ __forceinline__ void ldm_x4t(uint32_t r[4], unsigned addr) {
    asm volatile("ldmatrix.sync.aligned.m8n8.x4.trans.shared.b16 {%0,%1,%2,%3}, [%4];"
                 : "=r"(r[0]), "=r"(r[1]), "=r"(r[2]), "=r"(r[3]) : "r"(addr));
}
__device__ __forceinline__ void mma16816(float d[4], const uint32_t a[4],
                                         const uint32_t b0, const uint32_t b1) {
    asm volatile(
        "mma.sync.aligned.m16n8k16.row.col.f32.f16.f16.f32 "
        "{%0,%1,%2,%3}, {%4,%5,%6,%7}, {%8,%9}, {%0,%1,%2,%3};"
        : "+f"(d[0]), "+f"(d[1]), "+f"(d[2]), "+f"(d[3])
        : "r"(a[0]), "r"(a[1]), "r"(a[2]), "r"(a[3]), "r"(b0), "r"(b1));
}
__device__ __forceinline__ void cp16(unsigned dst, const void* src) {
    asm volatile("cp.async.cg.shared.global [%0], [%1], 16;"
                 :: "r"(dst), "l"(src));
}
#define CP_COMMIT() asm volatile("cp.async.commit_group;" ::: "memory")
#define CP_WAIT1()  asm volatile("cp.async.wait_group 1;" ::: "memory")

// ---------------------------------------------------------------------------
__global__ void cvt_h(const float* __restrict__ x, __half* __restrict__ h,
                      long n)
{
    long i = ((long)blockIdx.x * 256 + threadIdx.x) * 4;
    if (i >= n) return;
    float4 v = *(const float4*)(x + i);
    __half2 a = __floats2half2_rn(v.x, v.y);
    __half2 b = __floats2half2_rn(v.z, v.w);
    uint2 u;
    u.x = *(uint32_t*)&a; u.y = *(uint32_t*)&b;
    *(uint2*)(h + i) = u;
}

// ---------------------------------------------------------------------------
// Tensor-core GEMM (mma.sync fp16), 128 threads, 4 warps (2m x 2n),
// warp tile 64x64, BM=BN=128, BK=32, 3-stage cp.async, 2 CTAs/SM.
//   BTRANS=0: C = scale*(A[M,K] @ B[N,K]^T)+bias
//   BTRANS=1: C = scale*(A[M,K] @ B[K,N])+bias   (ldmatrix.trans)
// CSKIP: blocks above diagonal write fp32 zeros (attn upper triangle).
// CKLIM: K clamped to row0+128 (causal PV).
// ---------------------------------------------------------------------------
#define SST 40
#define BSTR 136
#define STG 3
#define B_OFF 10240u

template<bool CSKIP, bool CKLIM, bool BTRANS>
__global__ __launch_bounds__(128, 2)
void gemm_h(const __half* __restrict__ Ag, long sA,
            const __half* __restrict__ Bg, long sB,
            float* __restrict__ C, long sC,
            __half* __restrict__ Ch,
            int K, int lda, int ldb, int ldc, int Nvalid,
            const float* __restrict__ bias, float scale)
{
    constexpr unsigned STAGE = BTRANS ? (B_OFF + 32u * BSTR * 2u)   // 18944
                                      : (B_OFF + 128u * SST * 2u);  // 20480
    extern __shared__ __half sm[];

    const int bz = blockIdx.z;
    Ag += (long)bz * sA;
    Bg += (long)bz * sB;
    C  += (long)bz * sC;
    if (Ch) Ch += (long)bz * sC;

    const int row0 = blockIdx.y * 128;
    const int col0 = blockIdx.x * 128;
    const int tid = threadIdx.x;

    if (CSKIP && col0 >= row0 + 128) {
        // upper-triangle attn block: write fp32 zeros
        float* dst = C + (long)(row0 + tid) * ldc + col0;
        const float4 z = make_float4(0.f, 0.f, 0.f, 0.f);
#pragma unroll
        for (int i = 0; i < 32; i++) *(float4*)(dst + i * 4) = z;
        return;
    }

    const int kEnd = CKLIM ? min(K, row0 + 128) : K;
    const int nc = kEnd >> 5;

    const int wid = tid >> 5, lane = tid & 31;
    const int wm = wid & 1, wn = wid >> 1;

    // global load geometry
    const __half* pA = Ag + (long)(row0 + tid) * lda;     // 4 x 16B chunks
    const unsigned smb  = smem_u32(sm);
    const unsigned aoff = (unsigned)(tid * SST) * 2;

    const __half* pB;
    unsigned boff;
    if (BTRANS) {
        const int br = tid >> 2;               // 0..31 k-rows
        const int bq = (tid & 3) * 32;         // quarter-row, halves
        pB = Bg + (long)br * ldb + col0 + bq;
        boff = B_OFF + (unsigned)(br * BSTR + bq) * 2;
    } else {
        pB = Bg + (long)(col0 + tid) * ldb;
        boff = B_OFF + (unsigned)(tid * SST) * 2;
    }

    float acc[4][8][4];
#pragma unroll
    for (int i = 0; i < 4; i++)
#pragma unroll
        for (int j = 0; j < 8; j++)
#pragma unroll
            for (int k = 0; k < 4; k++) acc[i][j][k] = 0.f;

    auto load_stage = [&](int kc, int slot) {
        const int k0 = kc << 5;
        const unsigned so = smb + (unsigned)slot * STAGE;
#pragma unroll
        for (int q = 0; q < 4; q++)
            cp16(so + aoff + q * 16u, pA + k0 + q * 8);
        if (BTRANS) {
            const __half* b = pB + (long)k0 * ldb;
#pragma unroll
            for (int q = 0; q < 4; q++)
                cp16(so + boff + q * 16u, b + q * 8);
        } else {
#pragma unroll
            for (int q = 0; q < 4; q++)
                cp16(so + boff + q * 16u, pB + k0 + q * 8);
        }
    };

#pragma unroll
    for (int s = 0; s < STG - 1; s++) {
        if (s < nc) load_stage(s, s);
        CP_COMMIT();
    }

    const int a_ri = lane & 15;
    const int a_k8 = (lane >> 4) << 3;
    const int b_ri = (lane & 7) + ((lane >> 4) << 3);
    const int b_k8 = ((lane >> 3) & 1) << 3;
    const int t_kr = lane & 15;
    const int t_n8 = ((lane >> 4) & 1) << 3;

    for (int c = 0; c < nc; ++c) {
        CP_WAIT1();
        __syncthreads();

        const unsigned so = smb + (unsigned)(c % STG) * STAGE;
#pragma unroll
        for (int kk = 0; kk < 2; kk++) {
            uint32_t af[4][4];
#pragma unroll
            for (int mi = 0; mi < 4; mi++) {
                unsigned ad = so +
                    (unsigned)((wm * 64 + mi * 16 + a_ri) * SST + kk * 16 + a_k8) * 2;
                ldm_x4(af[mi], ad);
            }
#pragma unroll
            for (int g = 0; g < 4; g++) {
                uint32_t bf[4];
                if (BTRANS) {
                    unsigned bd = so + B_OFF +
                        (unsigned)((kk * 16 + t_kr) * BSTR +
                                   wn * 64 + g * 16 + t_n8) * 2;
                    ldm_x4t(bf, bd);
                } else {
                    unsigned bd = so + B_OFF +
                        (unsigned)((wn * 64 + g * 16 + b_ri) * SST + kk * 16 + b_k8) * 2;
                    ldm_x4(bf, bd);
                }
#pragma unroll
                for (int mi = 0; mi < 4; mi++) {
                    mma16816(acc[mi][2*g],   af[mi], bf[0], bf[1]);
                    mma16816(acc[mi][2*g+1], af[mi], bf[2], bf[3]);
                }
            }
        }
        const int nx = c + STG - 1;
        if (nx < nc) load_stage(nx, nx % STG);
        CP_COMMIT();
    }

    // epilogue
#pragma unroll
    for (int mi = 0; mi < 4; mi++) {
        const int rb = row0 + wm * 64 + mi * 16 + (lane >> 2);
#pragma unroll
        for (int f = 0; f < 8; f++) {
            const int cc = col0 + wn * 64 + f * 8 + ((lane & 3) << 1);
            if (cc >= Nvalid) continue;
            float b0 = 0.f, b1 = 0.f;
            if (bias) { b0 = bias[cc]; b1 = bias[cc + 1]; }
            float2 v0, v1;
            v0.x = acc[mi][f][0] * scale + b0;
            v0.y = acc[mi][f][1] * scale + b1;
            v1.x = acc[mi][f][2] * scale + b0;
            v1.y = acc[mi][f][3] * scale + b1;
            *(float2*)&C[(long)rb * ldc + cc]       = v0;
            *(float2*)&C[(long)(rb + 8) * ldc + cc] = v1;
            if (Ch) {
                __half2 h0 = __floats2half2_rn(v0.x, v0.y);
                __half2 h1 = __floats2half2_rn(v1.x, v1.y);
                *(uint32_t*)&Ch[(long)rb * ldc + cc]       = *(uint32_t*)&h0;
                *(uint32_t*)&Ch[(long)(rb + 8) * ldc + cc] = *(uint32_t*)&h1;
            }
        }
    }
}

// ---------------------------------------------------------------------------
__global__ void rmsnorm_h(const float* __restrict__ X,
                          const float* __restrict__ g,
                          __half* __restrict__ H, int n, int ldin)
{
    const float* x = X + (long)blockIdx.x * ldin;
    __half* h = H + (long)blockIdx.x * n;
    __shared__ float red[256];
    float s = 0.f;
    for (int i = threadIdx.x; i < n; i += 256) { float v = x[i]; s += v * v; }
    red[threadIdx.x] = s;
    __syncthreads();
    for (int o = 128; o > 0; o >>= 1) {
        if (threadIdx.x < o) red[threadIdx.x] += red[threadIdx.x + o];
        __syncthreads();
    }
    float r = rsqrtf(red[0] / (float)n + 1e-6f);
    for (int i = threadIdx.x; i < n; i += 256)
        h[i] = __float2half_rn(g[i] * x[i] * r);
}

// ---------------------------------------------------------------------------
__global__ void assemble_rope(const float* __restrict__ q,
                              const float* __restrict__ kvd,
                              const float* __restrict__ kv,
                              const int* __restrict__ pos_ids,
                              __half* __restrict__ qa,
                              __half* __restrict__ ka)
{
    const int s = blockIdx.x;
    const int t = threadIdx.x;
    __shared__ float cs[32], sn[32], kr[64];

    if (t < 32) {
        float pos = (float)pos_ids[s];
        double freq = exp(-log(10000.0) * (double)t / 32.0);
        float arg = pos * (float)freq;
        cs[t] = cosf(arg);
        sn[t] = sinf(arg);
    }
    __syncthreads();
    if (t < 32) {
        float x0 = kvd[(long)s * KVD_W + KVLR + 2 * t];
        float x1 = kvd[(long)s * KVD_W + KVLR + 2 * t + 1];
        kr[t]      = x0 * cs[t] - x1 * sn[t];
        kr[32 + t] = x1 * cs[t] + x0 * sn[t];
    }
    __syncthreads();

    for (int idx = t; idx < HEADS * QD; idx += 256) {
        int h = idx / QD, d = idx % QD;
        float qv, kvv;
        if (d < NOPE) {
            qv  = q[(long)s * QUP_N + h * QD + d];
            kvv = kv[(long)s * KUP_N + h * (NOPE + VD) + d];
        } else {
            int k = d - NOPE;
            int kk = k & 31;
            float x0 = q[(long)s * QUP_N + h * QD + NOPE + 2 * kk];
            float x1 = q[(long)s * QUP_N + h * QD + NOPE + 2 * kk + 1];
            qv = (k < 32) ? (x0 * cs[kk] - x1 * sn[kk])
                          : (x1 * cs[kk] + x0 * sn[kk]);
            kvv = kr[k];
        }
        long o = ((long)h * S_LEN + s) * QD + d;
        qa[o] = __float2half_rn(qv);
        ka[o] = __float2half_rn(kvv);
    }
}

// ---------------------------------------------------------------------------
// Causal softmax: single DRAM read via smem staging. Writes fp32 banded
// region + in-diagonal-block zeros (cols [n, band)); zeros beyond band are
// written by the QK kernel's skipped blocks. fp16 banded copy for PV.
// ---------------------------------------------------------------------------
__global__ void softmax_causal(float* __restrict__ attn,
                               __half* __restrict__ H)
{
    const long row = blockIdx.x;
    const int i = (int)(row & (S_LEN - 1));
    float* p = attn + row * S_LEN;
    __half* h = H + row * S_LEN;
    const int n = i + 1;
    const int band = ((i >> 7) + 1) << 7;
    __shared__ float srow[S_LEN];
    __shared__ float red[256];

    for (int j = threadIdx.x; j < n; j += 256) srow[j] = p[j];
    __syncthreads();

    float mx = -INFINITY;
    for (int j = threadIdx.x; j < n; j += 256) mx = fmaxf(mx, srow[j]);
    red[threadIdx.x] = mx;
    __syncthreads();
    for (int o = 128; o > 0; o >>= 1) {
        if (threadIdx.x < o)
            red[threadIdx.x] = fmaxf(red[threadIdx.x], red[threadIdx.x + o]);
        __syncthreads();
    }
    mx = red[0];
    __syncthreads();

    float s = 0.f;
    for (int j = threadIdx.x; j < n; j += 256) {
        float e = expf(srow[j] - mx);
        srow[j] = e;
        s += e;
    }
    red[threadIdx.x] = s;
    __syncthreads();
    for (int o = 128; o > 0; o >>= 1) {
        if (threadIdx.x < o) red[threadIdx.x] += red[threadIdx.x + o];
        __syncthreads();
    }
    float inv = 1.f / red[0];
    __syncthreads();

    for (int j = threadIdx.x; j < n; j += 256) {
        float v = srow[j] * inv;
        p[j] = v;
        h[j] = __float2half_rn(v);
    }
    __half z = __float2half_rn(0.f);
    for (int j = n + threadIdx.x; j < band; j += 256) { p[j] = 0.f; h[j] = z; }
}

// ---------------------------------------------------------------------------
extern "C" void kernel_launch(void* const* d_in, const int* in_sizes, int n_in,
                              void* d_out, int out_size)
{
    (void)in_sizes; (void)n_in; (void)out_size;
    const float* hid  = (const float*)d_in[0];
    const int*   pos  = (const int*)  d_in[1];
    const float* Wqd  = (const float*)d_in[3];
    const float* bqd  = (const float*)d_in[4];
    const float* gq   = (const float*)d_in[5];
    const float* Wqu  = (const float*)d_in[6];
    const float* Wkd  = (const float*)d_in[7];
    const float* bkd  = (const float*)d_in[8];
    const float* gkv  = (const float*)d_in[9];
    const float* Wku  = (const float*)d_in[10];
    const float* Wo   = (const float*)d_in[11];

    float* out  = (float*)d_out;
    float* attn = out + (long)S_LEN * HID;

    void *pf = nullptr, *ph = nullptr;
    cudaGetSymbolAddress(&pf, g_f32);
    cudaGetSymbolAddress(&ph, g_h16);
    float*  F = (float*)pf;
    __half* H = (__half*)ph;

    float* qraw = F + F_QRAW;
    float* qbuf = F + F_QBUF;
    float* kvd  = F + F_KVD;
    float* kv   = F + F_KV;

    const int SMEM_NT = STG * 20480;   // 61440
    const int SMEM_TR = STG * 18944;   // 56832
    static bool attr_done = false;
    if (!attr_done) {
        cudaFuncSetAttribute(gemm_h<false,false,false>,
            cudaFuncAttributeMaxDynamicSharedMemorySize, SMEM_NT);
        cudaFuncSetAttribute(gemm_h<true,false,false>,
            cudaFuncAttributeMaxDynamicSharedMemorySize, SMEM_NT);
        cudaFuncSetAttribute(gemm_h<false,true,true>,
            cudaFuncAttributeMaxDynamicSharedMemorySize, SMEM_TR);
        attr_done = true;
    }

    const dim3 blk(256);
    const dim3 gblk(128);
    const float qk_scale = 0.07216878364870323f;   // 1/sqrt(192)

    // 0. convert inputs to fp16 (Wkd into 640-row padded region)
    cvt_h<<<(unsigned)(((long)S_LEN*HID+1023)/1024), blk>>>(hid, H+O_HID, (long)S_LEN*HID);
    cvt_h<<<(unsigned)(((long)QLR*HID+1023)/1024), blk>>>(Wqd, H+O_WQD, (long)QLR*HID);
    cvt_h<<<(unsigned)(((long)QUP_N*QLR+1023)/1024), blk>>>(Wqu, H+O_WQU, (long)QUP_N*QLR);
    cvt_h<<<(unsigned)(((long)KVD_W*HID+1023)/1024), blk>>>(Wkd, H+O_WKD, (long)KVD_W*HID);
    cvt_h<<<(unsigned)(((long)KUP_N*KVLR+1023)/1024), blk>>>(Wku, H+O_WKU, (long)KUP_N*KVLR);
    cvt_h<<<(unsigned)(((long)HID*HEADS*VD+1023)/1024), blk>>>(Wo, H+O_WO, (long)HID*HEADS*VD);

    // 1. qraw = hid @ Wq_down^T + bq
    gemm_h<false,false,false><<<dim3(QLR/128, S_LEN/128, 1), gblk, SMEM_NT>>>(
        H+O_HID, 0, H+O_WQD, 0, qraw, 0, nullptr,
        HID, HID, HID, QLR, QLR, bqd, 1.f);
    // 2. rmsnorm -> fp16
    rmsnorm_h<<<S_LEN, blk>>>(qraw, gq, H+O_QRN, QLR, QLR);
    // 3. q = qrn @ Wq_up^T
    gemm_h<false,false,false><<<dim3(QUP_N/128, S_LEN/128, 1), gblk, SMEM_NT>>>(
        H+O_QRN, 0, H+O_WQU, 0, qbuf, 0, nullptr,
        QLR, QLR, QLR, QUP_N, QUP_N, nullptr, 1.f);
    // 4. kvd = hid @ Wkv_down^T + bkv  (N=576 via 640-padded weights)
    gemm_h<false,false,false><<<dim3(WKD_PAD/128, S_LEN/128, 1), gblk, SMEM_NT>>>(
        H+O_HID, 0, H+O_WKD, 0, kvd, 0, nullptr,
        HID, HID, HID, KVD_W, KVD_W, bkd, 1.f);
    // 5. rmsnorm first 512 cols -> fp16
    rmsnorm_h<<<S_LEN, blk>>>(kvd, gkv, H+O_KVN, KVLR, KVD_W);
    // 6. kv = kvn @ Wkv_up^T ; epilogue emits fp16 kv16 copy for PV
    gemm_h<false,false,false><<<dim3(KUP_N/128, S_LEN/128, 1), gblk, SMEM_NT>>>(
        H+O_KVN, 0, H+O_WKU, 0, kv, 0, H+O_KV16,
        KVLR, KVLR, KVLR, KUP_N, KUP_N, nullptr, 1.f);
    // 7. assemble + rope -> fp16 qall/kall
    assemble_rope<<<S_LEN, blk>>>(qbuf, kvd, kv, pos, H+O_QALL, H+O_KALL);
    // 8. scores -> attn fp32 (skipped blocks write the zero region)
    gemm_h<true,false,false><<<dim3(S_LEN/128, S_LEN/128, HEADS), gblk, SMEM_NT>>>(
        H+O_QALL, (long)S_LEN*QD, H+O_KALL, (long)S_LEN*QD,
        attn, (long)S_LEN*S_LEN, nullptr,
        QD, QD, QD, S_LEN, S_LEN, nullptr, qk_scale);
    // 9. causal softmax -> fp32 banded + fp16 banded
    softmax_causal<<<HEADS * S_LEN, blk>>>(attn, H+O_ATTN);
    // 10. ctx = attn @ v (NN gemm, K clamped); B = kv16 v-block.
    //     sC = VD: per-head offset for BOTH the scratch fp32 C (dead region
    //     F_KV, layout [S][H*VD] via ldc=HID) and fp16 ctx Ch.
    gemm_h<false,true,true><<<dim3(1, S_LEN/128, HEADS), gblk, SMEM_TR>>>(
        H+O_ATTN, (long)S_LEN*S_LEN,
        H+O_KV16 + NOPE, 256,
        F + F_KV, (long)VD, H+O_CTX,
        S_LEN, S_LEN, KUP_N, HID, VD, nullptr, 1.f);
    // 11. out = ctx @ Wo^T
    gemm_h<false,false,false><<<dim3(HID/128, S_LEN/128, 1), gblk, SMEM_NT>>>(
        H+O_CTX, 0, H+O_WO, 0, out, 0, nullptr,
        HID, HID, HID, HID, HID, nullptr, 1.f);
}

// round 12
// speedup vs baseline: 1.1421x; 1.1421x over previous
#include <cuda_runtime.h>
#include <cuda_fp16.h>
#include <math.h>
#include <stdint.h>

// ---------------------------------------------------------------------------
// DeepseekV2 MLA forward, B=1 S=2048 HID=2048 H=16 NOPE=128 ROPE=64 VD=128.
// Round 12: exact R8 GEMM engine (256 thr, 8 warps, 32x64 warp tiles — the
// measured local optimum; R11's 4-warp variant regressed). Single delta vs
// R8: QK's skipped upper-triangle blocks write the attn fp32 zeros, and
// softmax writes only the banded region (zero-fill off its critical path).
// ---------------------------------------------------------------------------

#define S_LEN 2048
#define HID   2048
#define HEADS 16
#define NOPE  128
#define ROPE  64
#define VD    128
#define QD    192
#define QLR   1536
#define KVLR  512
#define KVD_W (KVLR + 64)            // 576
#define QUP_N (HEADS * QD)           // 3072
#define KUP_N (HEADS * (NOPE + VD))  // 4096
#define WKD_PAD 640

// ---------------- fp32 scratch ----------------
#define F_QRAW 0L
#define F_QBUF (F_QRAW + (long)S_LEN * QLR)
#define F_KVD  (F_QBUF + (long)S_LEN * QUP_N)
#define F_KV   (F_KVD  + (long)S_LEN * KVD_W)
#define F_CTX  (F_KV   + (long)S_LEN * KUP_N)
#define F_TOT  (F_CTX  + (long)S_LEN * HID)

// ---------------- fp16 scratch ----------------
#define O_HID  0L
#define O_WQD  (O_HID  + (long)S_LEN * HID)
#define O_WQU  (O_WQD  + (long)QLR * HID)
#define O_WKD  (O_WQU  + (long)QUP_N * QLR)
#define O_WKU  (O_WKD  + (long)WKD_PAD * HID)
#define O_WO   (O_WKU  + (long)KUP_N * KVLR)
#define O_QRN  (O_WO   + (long)HID * (HEADS * VD))
#define O_KVN  (O_QRN  + (long)S_LEN * QLR)
#define O_QALL (O_KVN  + (long)S_LEN * KVLR)
#define O_KALL (O_QALL + (long)HEADS * S_LEN * QD)
#define O_KV16 (O_KALL + (long)HEADS * S_LEN * QD)
#define O_ATTN (O_KV16 + (long)S_LEN * KUP_N)
#define O_CTX  (O_ATTN + (long)HEADS * S_LEN * S_LEN)
#define O_TOT  (O_CTX  + (long)S_LEN * HID)

__device__ __align__(256) float  g_f32[F_TOT];
__device__ __align__(256) __half g_h16[O_TOT];

// ---------------------------------------------------------------------------
__device__ __forceinline__ unsigned smem_u32(const void* p) {
    return (unsigned)__cvta_generic_to_shared(p);
}
__device__ __forceinline__ void ldm_x4(uint32_t r[4], unsigned addr) {
    asm volatile("ldmatrix.sync.aligned.m8n8.x4.shared.b16 {%0,%1,%2,%3}, [%4];"
                 : "=r"(r[0]), "=r"(r[1]), "=r"(r[2]), "=r"(r[3]) : "r"(addr));
}
__device__ __forceinline__ void ldm_x4t(uint32_t r[4], unsigned addr) {
    asm volatile("ldmatrix.sync.aligned.m8n8.x4.trans.shared.b16 {%0,%1,%2,%3}, [%4];"
                 : "=r"(r[0]), "=r"(r[1]), "=r"(r[2]), "=r"(r[3]) : "r"(addr));
}
__device__ __forceinline__ void mma16816(float d[4], const uint32_t a[4],
                                         const uint32_t b0, const uint32_t b1) {
    asm volatile(
        "mma.sync.aligned.m16n8k16.row.col.f32.f16.f16.f32 "
        "{%0,%1,%2,%3}, {%4,%5,%6,%7}, {%8,%9}, {%0,%1,%2,%3};"
        : "+f"(d[0]), "+f"(d[1]), "+f"(d[2]), "+f"(d[3])
        : "r"(a[0]), "r"(a[1]), "r"(a[2]), "r"(a[3]), "r"(b0), "r"(b1));
}
__device__ __forceinline__ void cp16(unsigned dst, const void* src) {
    asm volatile("cp.async.cg.shared.global [%0], [%1], 16;"
                 :: "r"(dst), "l"(src));
}
#define CP_COMMIT() asm volatile("cp.async.commit_group;" ::: "memory")
#define CP_WAIT1()  asm volatile("cp.async.wait_group 1;" ::: "memory")

// ---------------------------------------------------------------------------
__global__ void cvt_h(const float* __restrict__ x, __half* __restrict__ h,
                      long n)
{
    long i = ((long)blockIdx.x * 256 + threadIdx.x) * 4;
    if (i >= n) return;
    float4 v = *(const float4*)(x + i);
    __half2 a = __floats2half2_rn(v.x, v.y);
    __half2 b = __floats2half2_rn(v.z, v.w);
    uint2 u;
    u.x = *(uint32_t*)&a; u.y = *(uint32_t*)&b;
    *(uint2*)(h + i) = u;
}

// ---------------------------------------------------------------------------
// Tensor-core GEMM (mma.sync fp16), 256 threads, 8 warps (4m x 2n),
// warp tile 32x64, BM=BN=128, BK=32, 3-stage cp.async, 2 CTAs/SM.
//   BTRANS=0: C = scale*(A[M,K] @ B[N,K]^T)+bias
//   BTRANS=1: C = scale*(A[M,K] @ B[K,N])+bias   (ldmatrix.trans)
// CSKIP: blocks above diagonal write fp32 zeros and return.
// CKLIM: K clamped to row0+128 (causal PV).
// ---------------------------------------------------------------------------
#define SST 40
#define BSTR 136
#define STG 3
#define B_OFF 10240u

template<bool CSKIP, bool CKLIM, bool BTRANS>
__global__ __launch_bounds__(256, 2)
void gemm_h(const __half* __restrict__ Ag, long sA,
            const __half* __restrict__ Bg, long sB,
            float* __restrict__ C, long sC,
            __half* __restrict__ Ch,
            int K, int lda, int ldb, int ldc, int Nvalid,
            const float* __restrict__ bias, float scale)
{
    constexpr unsigned STAGE = BTRANS ? (B_OFF + 32u * BSTR * 2u)   // 18944
                                      : (B_OFF + 128u * SST * 2u);  // 20480
    extern __shared__ __half sm[];

    const int bz = blockIdx.z;
    Ag += (long)bz * sA;
    Bg += (long)bz * sB;
    C  += (long)bz * sC;
    if (Ch) Ch += (long)bz * sC;

    const int row0 = blockIdx.y * 128;
    const int col0 = blockIdx.x * 128;
    const int tid = threadIdx.x;

    if (CSKIP && col0 >= row0 + 128) {
        // upper-triangle attn block: write fp32 zeros (hidden behind the
        // mma-bound compute blocks of the same launch)
        const int r = tid >> 1;
        float* dst = C + (long)(row0 + r) * ldc + col0 + (tid & 1) * 64;
        const float4 z = make_float4(0.f, 0.f, 0.f, 0.f);
#pragma unroll
        for (int i = 0; i < 16; i++) *(float4*)(dst + i * 4) = z;
        return;
    }

    const int kEnd = CKLIM ? min(K, row0 + 128) : K;
    const int nc = kEnd >> 5;

    const int wid = tid >> 5, lane = tid & 31;
    const int wm = wid & 3, wn = wid >> 2;

    // A global load: row tid/2, 32B chunk at (tid&1)*32B
    const int gr  = tid >> 1;
    const int gcb = (tid & 1) * 16;
    const __half* pA = Ag + (long)(row0 + gr) * lda + gcb;
    const unsigned smb  = smem_u32(sm);
    const unsigned aoff = (unsigned)(gr * SST + gcb) * 2;

    // B global load
    const __half* pB;
    unsigned boff;
    if (BTRANS) {
        const int br = tid >> 3;            // 0..31 (k rows)
        const int bc = (tid & 7) * 16;      // halves within 128-col row
        pB = Bg + (long)br * ldb + col0 + bc;
        boff = B_OFF + (unsigned)(br * BSTR + bc) * 2;
    } else {
        pB = Bg + (long)(col0 + gr) * ldb + gcb;
        boff = B_OFF + (unsigned)(gr * SST + gcb) * 2;
    }

    float acc[2][8][4];
#pragma unroll
    for (int i = 0; i < 2; i++)
#pragma unroll
        for (int j = 0; j < 8; j++)
#pragma unroll
            for (int k = 0; k < 4; k++) acc[i][j][k] = 0.f;

    auto load_stage = [&](int kc, int slot) {
        const int k0 = kc << 5;
        const unsigned so = smb + (unsigned)slot * STAGE;
        cp16(so + aoff,      pA + k0);
        cp16(so + aoff + 16, pA + k0 + 8);
        if (BTRANS) {
            const __half* b = pB + (long)k0 * ldb;
            cp16(so + boff,      b);
            cp16(so + boff + 16, b + 8);
        } else {
            cp16(so + boff,      pB + k0);
            cp16(so + boff + 16, pB + k0 + 8);
        }
    };

    // prologue: stages 0..STG-2
#pragma unroll
    for (int s = 0; s < STG - 1; s++) {
        if (s < nc) load_stage(s, s);
        CP_COMMIT();
    }

    // per-thread ldmatrix offsets
    const int a_ri = lane & 15;
    const int a_k8 = (lane >> 4) << 3;
    const int b_ri = (lane & 7) + ((lane >> 4) << 3);
    const int b_k8 = ((lane >> 3) & 1) << 3;
    const int t_kr = lane & 15;
    const int t_n8 = ((lane >> 4) & 1) << 3;

    for (int c = 0; c < nc; ++c) {
        CP_WAIT1();
        __syncthreads();

        const unsigned so = smb + (unsigned)(c % STG) * STAGE;
#pragma unroll
        for (int kk = 0; kk < 2; kk++) {
            uint32_t af[2][4];
#pragma unroll
            for (int mi = 0; mi < 2; mi++) {
                unsigned ad = so +
                    (unsigned)((wm * 32 + mi * 16 + a_ri) * SST + kk * 16 + a_k8) * 2;
                ldm_x4(af[mi], ad);
            }
#pragma unroll
            for (int g = 0; g < 4; g++) {
                uint32_t bf[4];
                if (BTRANS) {
                    unsigned bd = so + B_OFF +
                        (unsigned)((kk * 16 + t_kr) * BSTR +
                                   wn * 64 + g * 16 + t_n8) * 2;
                    ldm_x4t(bf, bd);
                } else {
                    unsigned bd = so + B_OFF +
                        (unsigned)((wn * 64 + g * 16 + b_ri) * SST + kk * 16 + b_k8) * 2;
                    ldm_x4(bf, bd);
                }
#pragma unroll
                for (int mi = 0; mi < 2; mi++) {
                    mma16816(acc[mi][2*g],   af[mi], bf[0], bf[1]);
                    mma16816(acc[mi][2*g+1], af[mi], bf[2], bf[3]);
                }
            }
        }
        // prefetch stage c+STG-1 into the slot freed by iteration c-1
        const int nx = c + STG - 1;
        if (nx < nc) load_stage(nx, nx % STG);
        CP_COMMIT();
    }

    // epilogue
#pragma unroll
    for (int mi = 0; mi < 2; mi++) {
        const int rb = row0 + wm * 32 + mi * 16 + (lane >> 2);
#pragma unroll
        for (int f = 0; f < 8; f++) {
            const int cc = col0 + wn * 64 + f * 8 + ((lane & 3) << 1);
            if (cc >= Nvalid) continue;
            float b0 = 0.f, b1 = 0.f;
            if (bias) { b0 = bias[cc]; b1 = bias[cc + 1]; }
            float2 v0, v1;
            v0.x = acc[mi][f][0] * scale + b0;
            v0.y = acc[mi][f][1] * scale + b1;
            v1.x = acc[mi][f][2] * scale + b0;
            v1.y = acc[mi][f][3] * scale + b1;
            *(float2*)&C[(long)rb * ldc + cc]       = v0;
            *(float2*)&C[(long)(rb + 8) * ldc + cc] = v1;
            if (Ch) {
                __half2 h0 = __floats2half2_rn(v0.x, v0.y);
                __half2 h1 = __floats2half2_rn(v1.x, v1.y);
                *(uint32_t*)&Ch[(long)rb * ldc + cc]       = *(uint32_t*)&h0;
                *(uint32_t*)&Ch[(long)(rb + 8) * ldc + cc] = *(uint32_t*)&h1;
            }
        }
    }
}

// ---------------------------------------------------------------------------
__global__ void rmsnorm_h(const float* __restrict__ X,
                          const float* __restrict__ g,
                          __half* __restrict__ H, int n, int ldin)
{
    const float* x = X + (long)blockIdx.x * ldin;
    __half* h = H + (long)blockIdx.x * n;
    __shared__ float red[256];
    float s = 0.f;
    for (int i = threadIdx.x; i < n; i += 256) { float v = x[i]; s += v * v; }
    red[threadIdx.x] = s;
    __syncthreads();
    for (int o = 128; o > 0; o >>= 1) {
        if (threadIdx.x < o) red[threadIdx.x] += red[threadIdx.x + o];
        __syncthreads();
    }
    float r = rsqrtf(red[0] / (float)n + 1e-6f);
    for (int i = threadIdx.x; i < n; i += 256)
        h[i] = __float2half_rn(g[i] * x[i] * r);
}

// ---------------------------------------------------------------------------
__global__ void assemble_rope(const float* __restrict__ q,
                              const float* __restrict__ kvd,
                              const float* __restrict__ kv,
                              const int* __restrict__ pos_ids,
                              __half* __restrict__ qa,
                              __half* __restrict__ ka)
{
    const int s = blockIdx.x;
    const int t = threadIdx.x;
    __shared__ float cs[32], sn[32], kr[64];

    if (t < 32) {
        float pos = (float)pos_ids[s];
        double freq = exp(-log(10000.0) * (double)t / 32.0);
        float arg = pos * (float)freq;
        cs[t] = cosf(arg);
        sn[t] = sinf(arg);
    }
    __syncthreads();
    if (t < 32) {
        float x0 = kvd[(long)s * KVD_W + KVLR + 2 * t];
        float x1 = kvd[(long)s * KVD_W + KVLR + 2 * t + 1];
        kr[t]      = x0 * cs[t] - x1 * sn[t];
        kr[32 + t] = x1 * cs[t] + x0 * sn[t];
    }
    __syncthreads();

    for (int idx = t; idx < HEADS * QD; idx += 256) {
        int h = idx / QD, d = idx % QD;
        float qv, kvv;
        if (d < NOPE) {
            qv  = q[(long)s * QUP_N + h * QD + d];
            kvv = kv[(long)s * KUP_N + h * (NOPE + VD) + d];
        } else {
            int k = d - NOPE;
            int kk = k & 31;
            float x0 = q[(long)s * QUP_N + h * QD + NOPE + 2 * kk];
            float x1 = q[(long)s * QUP_N + h * QD + NOPE + 2 * kk + 1];
            qv = (k < 32) ? (x0 * cs[kk] - x1 * sn[kk])
                          : (x1 * cs[kk] + x0 * sn[kk]);
            kvv = kr[k];
        }
        long o = ((long)h * S_LEN + s) * QD + d;
        qa[o] = __float2half_rn(qv);
        ka[o] = __float2half_rn(kvv);
    }
}

// ---------------------------------------------------------------------------
// Causal softmax: single DRAM read via smem staging. Writes the banded fp32
// region (cols [0, band)) and banded fp16; zeros beyond band are written by
// the QK kernel's skipped blocks.
// ---------------------------------------------------------------------------
__global__ void softmax_causal(float* __restrict__ attn,
                               __half* __restrict__ H)
{
    const long row = blockIdx.x;
    const int i = (int)(row & (S_LEN - 1));
    float* p = attn + row * S_LEN;
    __half* h = H + row * S_LEN;
    const int n = i + 1;
    const int band = ((i >> 7) + 1) << 7;
    __shared__ float srow[S_LEN];
    __shared__ float red[256];

    for (int j = threadIdx.x; j < n; j += 256) srow[j] = p[j];
    __syncthreads();

    float mx = -INFINITY;
    for (int j = threadIdx.x; j < n; j += 256) mx = fmaxf(mx, srow[j]);
    red[threadIdx.x] = mx;
    __syncthreads();
    for (int o = 128; o > 0; o >>= 1) {
        if (threadIdx.x < o)
            red[threadIdx.x] = fmaxf(red[threadIdx.x], red[threadIdx.x + o]);
        __syncthreads();
    }
    mx = red[0];
    __syncthreads();

    float s = 0.f;
    for (int j = threadIdx.x; j < n; j += 256) {
        float e = expf(srow[j] - mx);
        srow[j] = e;
        s += e;
    }
    red[threadIdx.x] = s;
    __syncthreads();
    for (int o = 128; o > 0; o >>= 1) {
        if (threadIdx.x < o) red[threadIdx.x] += red[threadIdx.x + o];
        __syncthreads();
    }
    float inv = 1.f / red[0];
    __syncthreads();

    for (int j = threadIdx.x; j < n; j += 256) {
        float v = srow[j] * inv;
        p[j] = v;
        h[j] = __float2half_rn(v);
    }
    __half z = __float2half_rn(0.f);
    for (int j = n + threadIdx.x; j < band; j += 256) { p[j] = 0.f; h[j] = z; }
}

// ---------------------------------------------------------------------------
extern "C" void kernel_launch(void* const* d_in, const int* in_sizes, int n_in,
                              void* d_out, int out_size)
{
    (void)in_sizes; (void)n_in; (void)out_size;
    const float* hid  = (const float*)d_in[0];
    const int*   pos  = (const int*)  d_in[1];
    const float* Wqd  = (const float*)d_in[3];
    const float* bqd  = (const float*)d_in[4];
    const float* gq   = (const float*)d_in[5];
    const float* Wqu  = (const float*)d_in[6];
    const float* Wkd  = (const float*)d_in[7];
    const float* bkd  = (const float*)d_in[8];
    const float* gkv  = (const float*)d_in[9];
    const float* Wku  = (const float*)d_in[10];
    const float* Wo   = (const float*)d_in[11];

    float* out  = (float*)d_out;
    float* attn = out + (long)S_LEN * HID;

    void *pf = nullptr, *ph = nullptr;
    cudaGetSymbolAddress(&pf, g_f32);
    cudaGetSymbolAddress(&ph, g_h16);
    float*  F = (float*)pf;
    __half* H = (__half*)ph;

    float* qraw = F + F_QRAW;
    float* qbuf = F + F_QBUF;
    float* kvd  = F + F_KVD;
    float* kv   = F + F_KV;
    float* ctx  = F + F_CTX;

    const int SMEM_NT = STG * 20480;   // 61440
    const int SMEM_TR = STG * 18944;   // 56832
    static bool attr_done = false;
    if (!attr_done) {
        cudaFuncSetAttribute(gemm_h<false,false,false>,
            cudaFuncAttributeMaxDynamicSharedMemorySize, SMEM_NT);
        cudaFuncSetAttribute(gemm_h<true,false,false>,
            cudaFuncAttributeMaxDynamicSharedMemorySize, SMEM_NT);
        cudaFuncSetAttribute(gemm_h<false,true,true>,
            cudaFuncAttributeMaxDynamicSharedMemorySize, SMEM_TR);
        attr_done = true;
    }

    const dim3 blk(256);
    const float qk_scale = 0.07216878364870323f;   // 1/sqrt(192)

    // 0. convert inputs to fp16 (Wkd into 640-row padded region)
    cvt_h<<<(unsigned)(((long)S_LEN*HID+1023)/1024), blk>>>(hid, H+O_HID, (long)S_LEN*HID);
    cvt_h<<<(unsigned)(((long)QLR*HID+1023)/1024), blk>>>(Wqd, H+O_WQD, (long)QLR*HID);
    cvt_h<<<(unsigned)(((long)QUP_N*QLR+1023)/1024), blk>>>(Wqu, H+O_WQU, (long)QUP_N*QLR);
    cvt_h<<<(unsigned)(((long)KVD_W*HID+1023)/1024), blk>>>(Wkd, H+O_WKD, (long)KVD_W*HID);
    cvt_h<<<(unsigned)(((long)KUP_N*KVLR+1023)/1024), blk>>>(Wku, H+O_WKU, (long)KUP_N*KVLR);
    cvt_h<<<(unsigned)(((long)HID*HEADS*VD+1023)/1024), blk>>>(Wo, H+O_WO, (long)HID*HEADS*VD);

    // 1. qraw = hid @ Wq_down^T + bq
    gemm_h<false,false,false><<<dim3(QLR/128, S_LEN/128, 1), blk, SMEM_NT>>>(
        H+O_HID, 0, H+O_WQD, 0, qraw, 0, nullptr,
        HID, HID, HID, QLR, QLR, bqd, 1.f);
    // 2. rmsnorm -> fp16
    rmsnorm_h<<<S_LEN, blk>>>(qraw, gq, H+O_QRN, QLR, QLR);
    // 3. q = qrn @ Wq_up^T
    gemm_h<false,false,false><<<dim3(QUP_N/128, S_LEN/128, 1), blk, SMEM_NT>>>(
        H+O_QRN, 0, H+O_WQU, 0, qbuf, 0, nullptr,
        QLR, QLR, QLR, QUP_N, QUP_N, nullptr, 1.f);
    // 4. kvd = hid @ Wkv_down^T + bkv  (N=576 via 640-padded weights)
    gemm_h<false,false,false><<<dim3(WKD_PAD/128, S_LEN/128, 1), blk, SMEM_NT>>>(
        H+O_HID, 0, H+O_WKD, 0, kvd, 0, nullptr,
        HID, HID, HID, KVD_W, KVD_W, bkd, 1.f);
    // 5. rmsnorm first 512 cols -> fp16
    rmsnorm_h<<<S_LEN, blk>>>(kvd, gkv, H+O_KVN, KVLR, KVD_W);
    // 6. kv = kvn @ Wkv_up^T ; epilogue emits fp16 kv16 copy for PV
    gemm_h<false,false,false><<<dim3(KUP_N/128, S_LEN/128, 1), blk, SMEM_NT>>>(
        H+O_KVN, 0, H+O_WKU, 0, kv, 0, H+O_KV16,
        KVLR, KVLR, KVLR, KUP_N, KUP_N, nullptr, 1.f);
    // 7. assemble + rope -> fp16 qall/kall
    assemble_rope<<<S_LEN, blk>>>(qbuf, kvd, kv, pos, H+O_QALL, H+O_KALL);
    // 8. scores -> attn fp32 (skipped blocks write the upper-triangle zeros)
    gemm_h<true,false,false><<<dim3(S_LEN/128, S_LEN/128, HEADS), blk, SMEM_NT>>>(
        H+O_QALL, (long)S_LEN*QD, H+O_KALL, (long)S_LEN*QD,
        attn, (long)S_LEN*S_LEN, nullptr,
        QD, QD, QD, S_LEN, S_LEN, nullptr, qk_scale);
    // 9. causal softmax -> fp32 banded + fp16 banded (single DRAM read)
    softmax_causal<<<HEADS * S_LEN, blk>>>(attn, H+O_ATTN);
    // 10. ctx = attn @ v (NN gemm, K clamped); B = kv16 v-block
    gemm_h<false,true,true><<<dim3(1, S_LEN/128, HEADS), blk, SMEM_TR>>>(
        H+O_ATTN, (long)S_LEN*S_LEN,
        H+O_KV16 + NOPE, 256,
        ctx, (long)VD, H+O_CTX,
        S_LEN, S_LEN, KUP_N, HID, VD, nullptr, 1.f);
    // 11. out = ctx @ Wo^T
    gemm_h<false,false,false><<<dim3(HID/128, S_LEN/128, 1), blk, SMEM_NT>>>(
        H+O_CTX, 0, H+O_WO, 0, out, 0, nullptr,
        HID, HID, HID, HID, HID, nullptr, 1.f);
}

// round 13
// speedup vs baseline: 1.1592x; 1.0150x over previous
#include <cuda_runtime.h>
#include <cuda_fp16.h>
#include <math.h>
#include <stdint.h>

// ---------------------------------------------------------------------------
// DeepseekV2 MLA forward, B=1 S=2048 HID=2048 H=16 NOPE=128 ROPE=64 VD=128.
// Round 13: exact R8 engine + two independent deltas:
//  (1) QK strictly-lower compute blocks write the mirrored upper-triangle
//      zero block in their epilogue (zeros spread across the launch, hidden
//      behind mma; R12's front-loaded standalone zero blocks regressed).
//      Softmax zero-fills only the in-diagonal-block band.
//  (2) PV split-K: bottom-half row blocks split K into two halves (fp32
//      partials + tiny combine kernel) -> longest PV chain 64 -> 32 chunks.
// ---------------------------------------------------------------------------

#define S_LEN 2048
#define HID   2048
#define HEADS 16
#define NOPE  128
#define ROPE  64
#define VD    128
#define QD    192
#define QLR   1536
#define KVLR  512
#define KVD_W (KVLR + 64)            // 576
#define QUP_N (HEADS * QD)           // 3072
#define KUP_N (HEADS * (NOPE + VD))  // 4096
#define WKD_PAD 640

// ---------------- fp32 scratch ----------------
#define F_QRAW 0L
#define F_QBUF (F_QRAW + (long)S_LEN * QLR)
#define F_KVD  (F_QBUF + (long)S_LEN * QUP_N)
#define F_KV   (F_KVD  + (long)S_LEN * KVD_W)
#define F_CTX  (F_KV   + (long)S_LEN * KUP_N)
#define F_CT2  (F_CTX  + (long)S_LEN * HID)              // split-K partials
#define F_TOT  (F_CT2  + 2L * S_LEN * HID)

// ---------------- fp16 scratch ----------------
#define O_HID  0L
#define O_WQD  (O_HID  + (long)S_LEN * HID)
#define O_WQU  (O_WQD  + (long)QLR * HID)
#define O_WKD  (O_WQU  + (long)QUP_N * QLR)
#define O_WKU  (O_WKD  + (long)WKD_PAD * HID)
#define O_WO   (O_WKU  + (long)KUP_N * KVLR)
#define O_QRN  (O_WO   + (long)HID * (HEADS * VD))
#define O_KVN  (O_QRN  + (long)S_LEN * QLR)
#define O_QALL (O_KVN  + (long)S_LEN * KVLR)
#define O_KALL (O_QALL + (long)HEADS * S_LEN * QD)
#define O_KV16 (O_KALL + (long)HEADS * S_LEN * QD)
#define O_ATTN (O_KV16 + (long)S_LEN * KUP_N)
#define O_CTX  (O_ATTN + (long)HEADS * S_LEN * S_LEN)
#define O_TOT  (O_CTX  + (long)S_LEN * HID)

__device__ __align__(256) float  g_f32[F_TOT];
__device__ __align__(256) __half g_h16[O_TOT];

// ---------------------------------------------------------------------------
__device__ __forceinline__ unsigned smem_u32(const void* p) {
    return (unsigned)__cvta_generic_to_shared(p);
}
__device__ __forceinline__ void ldm_x4(uint32_t r[4], unsigned addr) {
    asm volatile("ldmatrix.sync.aligned.m8n8.x4.shared.b16 {%0,%1,%2,%3}, [%4];"
                 : "=r"(r[0]), "=r"(r[1]), "=r"(r[2]), "=r"(r[3]) : "r"(addr));
}
__device__ __forceinline__ void ldm_x4t(uint32_t r[4], unsigned addr) {
    asm volatile("ldmatrix.sync.aligned.m8n8.x4.trans.shared.b16 {%0,%1,%2,%3}, [%4];"
                 : "=r"(r[0]), "=r"(r[1]), "=r"(r[2]), "=r"(r[3]) : "r"(addr));
}
__device__ __forceinline__ void mma16816(float d[4], const uint32_t a[4],
                                         const uint32_t b0, const uint32_t b1) {
    asm volatile(
        "mma.sync.aligned.m16n8k16.row.col.f32.f16.f16.f32 "
        "{%0,%1,%2,%3}, {%4,%5,%6,%7}, {%8,%9}, {%0,%1,%2,%3};"
        : "+f"(d[0]), "+f"(d[1]), "+f"(d[2]), "+f"(d[3])
        : "r"(a[0]), "r"(a[1]), "r"(a[2]), "r"(a[3]), "r"(b0), "r"(b1));
}
__device__ __forceinline__ void cp16(unsigned dst, const void* src) {
    asm volatile("cp.async.cg.shared.global [%0], [%1], 16;"
                 :: "r"(dst), "l"(src));
}
#define CP_COMMIT() asm volatile("cp.async.commit_group;" ::: "memory")
#define CP_WAIT1()  asm volatile("cp.async.wait_group 1;" ::: "memory")

// ---------------------------------------------------------------------------
__global__ void cvt_h(const float* __restrict__ x, __half* __restrict__ h,
                      long n)
{
    long i = ((long)blockIdx.x * 256 + threadIdx.x) * 4;
    if (i >= n) return;
    float4 v = *(const float4*)(x + i);
    __half2 a = __floats2half2_rn(v.x, v.y);
    __half2 b = __floats2half2_rn(v.z, v.w);
    uint2 u;
    u.x = *(uint32_t*)&a; u.y = *(uint32_t*)&b;
    *(uint2*)(h + i) = u;
}

// ---------------------------------------------------------------------------
// Tensor-core GEMM (mma.sync fp16), 256 threads, 8 warps (4m x 2n),
// warp tile 32x64, BM=BN=128, BK=32, 3-stage cp.async, 2 CTAs/SM.
//   BTRANS=0: C = scale*(A[M,K] @ B[N,K]^T)+bias
//   BTRANS=1: C = scale*(A[M,K] @ B[K,N])+bias   (ldmatrix.trans)
// CSKIP: skip blocks above diagonal; strictly-lower blocks also write the
//        mirrored upper-triangle zero block in their epilogue.
// CKLIM: K clamped to row0+128 (causal PV).
// SPLITK: PV split-K. col0=0, blockIdx.x = K-half. Rows < S/2: single block
//         (x=0) writes fp16 ctx. Rows >= S/2: x in {0,1} write fp32 partials
//         to split[x]; combined by combine_ctx.
// ---------------------------------------------------------------------------
#define SST 40
#define BSTR 136
#define STG 3
#define B_OFF 10240u

template<bool CSKIP, bool CKLIM, bool BTRANS, bool SPLITK>
__global__ __launch_bounds__(256, 2)
void gemm_h(const __half* __restrict__ Ag, long sA,
            const __half* __restrict__ Bg, long sB,
            float* __restrict__ C, long sC,
            __half* __restrict__ Ch,
            int K, int lda, int ldb, int ldc, int Nvalid,
            const float* __restrict__ bias, float scale,
            float* __restrict__ split)
{
    constexpr unsigned STAGE = BTRANS ? (B_OFF + 32u * BSTR * 2u)   // 18944
                                      : (B_OFF + 128u * SST * 2u);  // 20480
    extern __shared__ __half sm[];

    const int bz = blockIdx.z;
    Ag += (long)bz * sA;
    Bg += (long)bz * sB;
    C  += (long)bz * sC;
    if (Ch) Ch += (long)bz * sC;

    const int row0 = blockIdx.y * 128;
    const int col0 = SPLITK ? 0 : blockIdx.x * 128;
    const int tid = threadIdx.x;

    if (CSKIP && col0 >= row0 + 128) return;   // upper triangle: no work here

    int kStart = 0;
    int kEnd = CKLIM ? min(K, row0 + 128) : K;
    bool partial = false;
    if (SPLITK) {
        if (row0 < S_LEN / 2) {
            if (blockIdx.x) return;            // single block covers all K
        } else {
            partial = true;
            if (blockIdx.x == 0) kEnd = S_LEN / 2;
            else                 kStart = S_LEN / 2;
        }
    }
    const int nc = (kEnd - kStart) >> 5;

    const int wid = tid >> 5, lane = tid & 31;
    const int wm = wid & 3, wn = wid >> 2;

    // A global load: row tid/2, 32B chunk at (tid&1)*32B
    const int gr  = tid >> 1;
    const int gcb = (tid & 1) * 16;
    const __half* pA = Ag + (long)(row0 + gr) * lda + gcb;
    const unsigned smb  = smem_u32(sm);
    const unsigned aoff = (unsigned)(gr * SST + gcb) * 2;

    // B global load
    const __half* pB;
    unsigned boff;
    if (BTRANS) {
        const int br = tid >> 3;            // 0..31 (k rows)
        const int bc = (tid & 7) * 16;      // halves within 128-col row
        pB = Bg + (long)br * ldb + col0 + bc;
        boff = B_OFF + (unsigned)(br * BSTR + bc) * 2;
    } else {
        pB = Bg + (long)(col0 + gr) * ldb + gcb;
        boff = B_OFF + (unsigned)(gr * SST + gcb) * 2;
    }

    float acc[2][8][4];
#pragma unroll
    for (int i = 0; i < 2; i++)
#pragma unroll
        for (int j = 0; j < 8; j++)
#pragma unroll
            for (int k = 0; k < 4; k++) acc[i][j][k] = 0.f;

    auto load_stage = [&](int kc, int slot) {
        const int k0 = kStart + (kc << 5);
        const unsigned so = smb + (unsigned)slot * STAGE;
        cp16(so + aoff,      pA + k0);
        cp16(so + aoff + 16, pA + k0 + 8);
        if (BTRANS) {
            const __half* b = pB + (long)k0 * ldb;
            cp16(so + boff,      b);
            cp16(so + boff + 16, b + 8);
        } else {
            cp16(so + boff,      pB + k0);
            cp16(so + boff + 16, pB + k0 + 8);
        }
    };

    // prologue: stages 0..STG-2
#pragma unroll
    for (int s = 0; s < STG - 1; s++) {
        if (s < nc) load_stage(s, s);
        CP_COMMIT();
    }

    // per-thread ldmatrix offsets
    const int a_ri = lane & 15;
    const int a_k8 = (lane >> 4) << 3;
    const int b_ri = (lane & 7) + ((lane >> 4) << 3);
    const int b_k8 = ((lane >> 3) & 1) << 3;
    const int t_kr = lane & 15;
    const int t_n8 = ((lane >> 4) & 1) << 3;

    for (int c = 0; c < nc; ++c) {
        CP_WAIT1();
        __syncthreads();

        const unsigned so = smb + (unsigned)(c % STG) * STAGE;
#pragma unroll
        for (int kk = 0; kk < 2; kk++) {
            uint32_t af[2][4];
#pragma unroll
            for (int mi = 0; mi < 2; mi++) {
                unsigned ad = so +
                    (unsigned)((wm * 32 + mi * 16 + a_ri) * SST + kk * 16 + a_k8) * 2;
                ldm_x4(af[mi], ad);
            }
#pragma unroll
            for (int g = 0; g < 4; g++) {
                uint32_t bf[4];
                if (BTRANS) {
                    unsigned bd = so + B_OFF +
                        (unsigned)((kk * 16 + t_kr) * BSTR +
                                   wn * 64 + g * 16 + t_n8) * 2;
                    ldm_x4t(bf, bd);
                } else {
                    unsigned bd = so + B_OFF +
                        (unsigned)((wn * 64 + g * 16 + b_ri) * SST + kk * 16 + b_k8) * 2;
                    ldm_x4(bf, bd);
                }
#pragma unroll
                for (int mi = 0; mi < 2; mi++) {
                    mma16816(acc[mi][2*g],   af[mi], bf[0], bf[1]);
                    mma16816(acc[mi][2*g+1], af[mi], bf[2], bf[3]);
                }
            }
        }
        // prefetch stage c+STG-1 into the slot freed by iteration c-1
        const int nx = c + STG - 1;
        if (nx < nc) load_stage(nx, nx % STG);
        CP_COMMIT();
    }

    // epilogue
    float* dstP = nullptr;
    if (SPLITK)
        dstP = split + (long)blockIdx.x * S_LEN * HID + (long)bz * VD;
#pragma unroll
    for (int mi = 0; mi < 2; mi++) {
        const int rb = row0 + wm * 32 + mi * 16 + (lane >> 2);
#pragma unroll
        for (int f = 0; f < 8; f++) {
            const int cc = col0 + wn * 64 + f * 8 + ((lane & 3) << 1);
            if (cc >= Nvalid) continue;
            float b0 = 0.f, b1 = 0.f;
            if (bias) { b0 = bias[cc]; b1 = bias[cc + 1]; }
            float2 v0, v1;
            v0.x = acc[mi][f][0] * scale + b0;
            v0.y = acc[mi][f][1] * scale + b1;
            v1.x = acc[mi][f][2] * scale + b0;
            v1.y = acc[mi][f][3] * scale + b1;
            if (SPLITK && partial) {
                *(float2*)&dstP[(long)rb * ldc + cc]       = v0;
                *(float2*)&dstP[(long)(rb + 8) * ldc + cc] = v1;
                continue;
            }
            *(float2*)&C[(long)rb * ldc + cc]       = v0;
            *(float2*)&C[(long)(rb + 8) * ldc + cc] = v1;
            if (Ch) {
                __half2 h0 = __floats2half2_rn(v0.x, v0.y);
                __half2 h1 = __floats2half2_rn(v1.x, v1.y);
                *(uint32_t*)&Ch[(long)rb * ldc + cc]       = *(uint32_t*)&h0;
                *(uint32_t*)&Ch[(long)(rb + 8) * ldc + cc] = *(uint32_t*)&h1;
            }
        }
    }

    // CSKIP: strictly-lower blocks write the mirrored upper-triangle zeros.
    // Spread across the launch (after ~6 chunks of mma per block), so the
    // stores hide behind other CTAs' compute instead of front-loading DRAM.
    if (CSKIP && col0 + 128 <= row0) {
        const int r = tid >> 1;
        float* dst = C + (long)(col0 + r) * ldc + row0 + (tid & 1) * 64;
        const float4 z = make_float4(0.f, 0.f, 0.f, 0.f);
#pragma unroll
        for (int i = 0; i < 16; i++) *(float4*)(dst + i * 4) = z;
    }
}

// ---------------------------------------------------------------------------
// combine split-K partials for ctx rows [S/2, S): ctx16 = fp16(P0 + P1)
// ---------------------------------------------------------------------------
__global__ void combine_ctx(const float* __restrict__ P0,
                            const float* __restrict__ P1,
                            __half* __restrict__ ctx)
{
    const long base = (long)(S_LEN / 2) * HID;
    long i = ((long)blockIdx.x * 256 + threadIdx.x) * 4;
    float4 a = *(const float4*)(P0 + base + i);
    float4 b = *(const float4*)(P1 + base + i);
    __half2 h0 = __floats2half2_rn(a.x + b.x, a.y + b.y);
    __half2 h1 = __floats2half2_rn(a.z + b.z, a.w + b.w);
    uint2 u;
    u.x = *(uint32_t*)&h0; u.y = *(uint32_t*)&h1;
    *(uint2*)(ctx + base + i) = u;
}

// ---------------------------------------------------------------------------
__global__ void rmsnorm_h(const float* __restrict__ X,
                          const float* __restrict__ g,
                          __half* __restrict__ H, int n, int ldin)
{
    const float* x = X + (long)blockIdx.x * ldin;
    __half* h = H + (long)blockIdx.x * n;
    __shared__ float red[256];
    float s = 0.f;
    for (int i = threadIdx.x; i < n; i += 256) { float v = x[i]; s += v * v; }
    red[threadIdx.x] = s;
    __syncthreads();
    for (int o = 128; o > 0; o >>= 1) {
        if (threadIdx.x < o) red[threadIdx.x] += red[threadIdx.x + o];
        __syncthreads();
    }
    float r = rsqrtf(red[0] / (float)n + 1e-6f);
    for (int i = threadIdx.x; i < n; i += 256)
        h[i] = __float2half_rn(g[i] * x[i] * r);
}

// ---------------------------------------------------------------------------
__global__ void assemble_rope(const float* __restrict__ q,
                              const float* __restrict__ kvd,
                              const float* __restrict__ kv,
                              const int* __restrict__ pos_ids,
                              __half* __restrict__ qa,
                              __half* __restrict__ ka)
{
    const int s = blockIdx.x;
    const int t = threadIdx.x;
    __shared__ float cs[32], sn[32], kr[64];

    if (t < 32) {
        float pos = (float)pos_ids[s];
        double freq = exp(-log(10000.0) * (double)t / 32.0);
        float arg = pos * (float)freq;
        cs[t] = cosf(arg);
        sn[t] = sinf(arg);
    }
    __syncthreads();
    if (t < 32) {
        float x0 = kvd[(long)s * KVD_W + KVLR + 2 * t];
        float x1 = kvd[(long)s * KVD_W + KVLR + 2 * t + 1];
        kr[t]      = x0 * cs[t] - x1 * sn[t];
        kr[32 + t] = x1 * cs[t] + x0 * sn[t];
    }
    __syncthreads();

    for (int idx = t; idx < HEADS * QD; idx += 256) {
        int h = idx / QD, d = idx % QD;
        float qv, kvv;
        if (d < NOPE) {
            qv  = q[(long)s * QUP_N + h * QD + d];
            kvv = kv[(long)s * KUP_N + h * (NOPE + VD) + d];
        } else {
            int k = d - NOPE;
            int kk = k & 31;
            float x0 = q[(long)s * QUP_N + h * QD + NOPE + 2 * kk];
            float x1 = q[(long)s * QUP_N + h * QD + NOPE + 2 * kk + 1];
            qv = (k < 32) ? (x0 * cs[kk] - x1 * sn[kk])
                          : (x1 * cs[kk] + x0 * sn[kk]);
            kvv = kr[k];
        }
        long o = ((long)h * S_LEN + s) * QD + d;
        qa[o] = __float2half_rn(qv);
        ka[o] = __float2half_rn(kvv);
    }
}

// ---------------------------------------------------------------------------
// Causal softmax: single DRAM read via smem staging. Writes banded fp32 +
// fp16 and in-diagonal-block zeros [n, band); zeros beyond band are written
// by QK compute blocks' mirrored epilogues.
// ---------------------------------------------------------------------------
__global__ void softmax_causal(float* __restrict__ attn,
                               __half* __restrict__ H)
{
    const long row = blockIdx.x;
    const int i = (int)(row & (S_LEN - 1));
    float* p = attn + row * S_LEN;
    __half* h = H + row * S_LEN;
    const int n = i + 1;
    const int band = ((i >> 7) + 1) << 7;
    __shared__ float srow[S_LEN];
    __shared__ float red[256];

    for (int j = threadIdx.x; j < n; j += 256) srow[j] = p[j];
    __syncthreads();

    float mx = -INFINITY;
    for (int j = threadIdx.x; j < n; j += 256) mx = fmaxf(mx, srow[j]);
    red[threadIdx.x] = mx;
    __syncthreads();
    for (int o = 128; o > 0; o >>= 1) {
        if (threadIdx.x < o)
            red[threadIdx.x] = fmaxf(red[threadIdx.x], red[threadIdx.x + o]);
        __syncthreads();
    }
    mx = red[0];
    __syncthreads();

    float s = 0.f;
    for (int j = threadIdx.x; j < n; j += 256) {
        float e = expf(srow[j] - mx);
        srow[j] = e;
        s += e;
    }
    red[threadIdx.x] = s;
    __syncthreads();
    for (int o = 128; o > 0; o >>= 1) {
        if (threadIdx.x < o) red[threadIdx.x] += red[threadIdx.x + o];
        __syncthreads();
    }
    float inv = 1.f / red[0];
    __syncthreads();

    for (int j = threadIdx.x; j < n; j += 256) {
        float v = srow[j] * inv;
        p[j] = v;
        h[j] = __float2half_rn(v);
    }
    __half z = __float2half_rn(0.f);
    for (int j = n + threadIdx.x; j < band; j += 256) { p[j] = 0.f; h[j] = z; }
}

// ---------------------------------------------------------------------------
extern "C" void kernel_launch(void* const* d_in, const int* in_sizes, int n_in,
                              void* d_out, int out_size)
{
    (void)in_sizes; (void)n_in; (void)out_size;
    const float* hid  = (const float*)d_in[0];
    const int*   pos  = (const int*)  d_in[1];
    const float* Wqd  = (const float*)d_in[3];
    const float* bqd  = (const float*)d_in[4];
    const float* gq   = (const float*)d_in[5];
    const float* Wqu  = (const float*)d_in[6];
    const float* Wkd  = (const float*)d_in[7];
    const float* bkd  = (const float*)d_in[8];
    const float* gkv  = (const float*)d_in[9];
    const float* Wku  = (const float*)d_in[10];
    const float* Wo   = (const float*)d_in[11];

    float* out  = (float*)d_out;
    float* attn = out + (long)S_LEN * HID;

    void *pf = nullptr, *ph = nullptr;
    cudaGetSymbolAddress(&pf, g_f32);
    cudaGetSymbolAddress(&ph, g_h16);
    float*  F = (float*)pf;
    __half* H = (__half*)ph;

    float* qraw = F + F_QRAW;
    float* qbuf = F + F_QBUF;
    float* kvd  = F + F_KVD;
    float* kv   = F + F_KV;
    float* ctx  = F + F_CTX;
    float* psk  = F + F_CT2;           // split-K partial base (2 buffers)

    const int SMEM_NT = STG * 20480;   // 61440
    const int SMEM_TR = STG * 18944;   // 56832
    static bool attr_done = false;
    if (!attr_done) {
        cudaFuncSetAttribute(gemm_h<false,false,false,false>,
            cudaFuncAttributeMaxDynamicSharedMemorySize, SMEM_NT);
        cudaFuncSetAttribute(gemm_h<true,false,false,false>,
            cudaFuncAttributeMaxDynamicSharedMemorySize, SMEM_NT);
        cudaFuncSetAttribute(gemm_h<false,true,true,true>,
            cudaFuncAttributeMaxDynamicSharedMemorySize, SMEM_TR);
        attr_done = true;
    }

    const dim3 blk(256);
    const float qk_scale = 0.07216878364870323f;   // 1/sqrt(192)

    // 0. convert inputs to fp16 (Wkd into 640-row padded region)
    cvt_h<<<(unsigned)(((long)S_LEN*HID+1023)/1024), blk>>>(hid, H+O_HID, (long)S_LEN*HID);
    cvt_h<<<(unsigned)(((long)QLR*HID+1023)/1024), blk>>>(Wqd, H+O_WQD, (long)QLR*HID);
    cvt_h<<<(unsigned)(((long)QUP_N*QLR+1023)/1024), blk>>>(Wqu, H+O_WQU, (long)QUP_N*QLR);
    cvt_h<<<(unsigned)(((long)KVD_W*HID+1023)/1024), blk>>>(Wkd, H+O_WKD, (long)KVD_W*HID);
    cvt_h<<<(unsigned)(((long)KUP_N*KVLR+1023)/1024), blk>>>(Wku, H+O_WKU, (long)KUP_N*KVLR);
    cvt_h<<<(unsigned)(((long)HID*HEADS*VD+1023)/1024), blk>>>(Wo, H+O_WO, (long)HID*HEADS*VD);

    // 1. qraw = hid @ Wq_down^T + bq
    gemm_h<false,false,false,false><<<dim3(QLR/128, S_LEN/128, 1), blk, SMEM_NT>>>(
        H+O_HID, 0, H+O_WQD, 0, qraw, 0, nullptr,
        HID, HID, HID, QLR, QLR, bqd, 1.f, nullptr);
    // 2. rmsnorm -> fp16
    rmsnorm_h<<<S_LEN, blk>>>(qraw, gq, H+O_QRN, QLR, QLR);
    // 3. q = qrn @ Wq_up^T
    gemm_h<false,false,false,false><<<dim3(QUP_N/128, S_LEN/128, 1), blk, SMEM_NT>>>(
        H+O_QRN, 0, H+O_WQU, 0, qbuf, 0, nullptr,
        QLR, QLR, QLR, QUP_N, QUP_N, nullptr, 1.f, nullptr);
    // 4. kvd = hid @ Wkv_down^T + bkv  (N=576 via 640-padded weights)
    gemm_h<false,false,false,false><<<dim3(WKD_PAD/128, S_LEN/128, 1), blk, SMEM_NT>>>(
        H+O_HID, 0, H+O_WKD, 0, kvd, 0, nullptr,
        HID, HID, HID, KVD_W, KVD_W, bkd, 1.f, nullptr);
    // 5. rmsnorm first 512 cols -> fp16
    rmsnorm_h<<<S_LEN, blk>>>(kvd, gkv, H+O_KVN, KVLR, KVD_W);
    // 6. kv = kvn @ Wkv_up^T ; epilogue emits fp16 kv16 copy for PV
    gemm_h<false,false,false,false><<<dim3(KUP_N/128, S_LEN/128, 1), blk, SMEM_NT>>>(
        H+O_KVN, 0, H+O_WKU, 0, kv, 0, H+O_KV16,
        KVLR, KVLR, KVLR, KUP_N, KUP_N, nullptr, 1.f, nullptr);
    // 7. assemble + rope -> fp16 qall/kall
    assemble_rope<<<S_LEN, blk>>>(qbuf, kvd, kv, pos, H+O_QALL, H+O_KALL);
    // 8. scores -> attn fp32; strictly-lower compute blocks also write the
    //    mirrored upper-triangle zero block
    gemm_h<true,false,false,false><<<dim3(S_LEN/128, S_LEN/128, HEADS), blk, SMEM_NT>>>(
        H+O_QALL, (long)S_LEN*QD, H+O_KALL, (long)S_LEN*QD,
        attn, (long)S_LEN*S_LEN, nullptr,
        QD, QD, QD, S_LEN, S_LEN, nullptr, qk_scale, nullptr);
    // 9. causal softmax -> fp32/fp16 banded (single DRAM read)
    softmax_causal<<<HEADS * S_LEN, blk>>>(attn, H+O_ATTN);
    // 10. PV split-K: grid.x = K-half. Top rows: direct fp16 ctx.
    //     Bottom rows: fp32 partials to psk[0..1].
    gemm_h<false,true,true,true><<<dim3(2, S_LEN/128, HEADS), blk, SMEM_TR>>>(
        H+O_ATTN, (long)S_LEN*S_LEN,
        H+O_KV16 + NOPE, 256,
        ctx, (long)VD, H+O_CTX,
        S_LEN, S_LEN, KUP_N, HID, VD, nullptr, 1.f, psk);
    // 10b. combine bottom-half partials -> fp16 ctx
    combine_ctx<<<(S_LEN/2) * HID / 1024, blk>>>(psk, psk + (long)S_LEN*HID, H+O_CTX);
    // 11. out = ctx @ Wo^T
    gemm_h<false,false,false,false><<<dim3(HID/128, S_LEN/128, 1), blk, SMEM_NT>>>(
        H+O_CTX, 0, H+O_WO, 0, out, 0, nullptr,
        HID, HID, HID, HID, HID, nullptr, 1.f, nullptr);
}

// round 14
// speedup vs baseline: 1.2037x; 1.0384x over previous
#include <cuda_runtime.h>
#include <cuda_fp16.h>
#include <math.h>
#include <stdint.h>

// ---------------------------------------------------------------------------
// DeepseekV2 MLA forward, B=1 S=2048 HID=2048 H=16 NOPE=128 ROPE=64 VD=128.
// Round 14: exact R8 (668us baseline) + ONE isolated delta: PV split-K.
// Bottom-half row blocks (row0 >= S/2) split K into two halves writing fp32
// partials; combine_ctx sums them into fp16 ctx. Longest PV chain 64 -> 32
// chunks. Softmax/zero-fill structure untouched (R9-R13 showed any change
// there regresses).
// ---------------------------------------------------------------------------

#define S_LEN 2048
#define HID   2048
#define HEADS 16
#define NOPE  128
#define ROPE  64
#define VD    128
#define QD    192
#define QLR   1536
#define KVLR  512
#define KVD_W (KVLR + 64)            // 576
#define QUP_N (HEADS * QD)           // 3072
#define KUP_N (HEADS * (NOPE + VD))  // 4096
#define WKD_PAD 640

// ---------------- fp32 scratch ----------------
#define F_QRAW 0L
#define F_QBUF (F_QRAW + (long)S_LEN * QLR)
#define F_KVD  (F_QBUF + (long)S_LEN * QUP_N)
#define F_KV   (F_KVD  + (long)S_LEN * KVD_W)
#define F_CTX  (F_KV   + (long)S_LEN * KUP_N)
#define F_CT2  (F_CTX  + (long)S_LEN * HID)              // split-K partials
#define F_TOT  (F_CT2  + 2L * S_LEN * HID)

// ---------------- fp16 scratch ----------------
#define O_HID  0L
#define O_WQD  (O_HID  + (long)S_LEN * HID)
#define O_WQU  (O_WQD  + (long)QLR * HID)
#define O_WKD  (O_WQU  + (long)QUP_N * QLR)
#define O_WKU  (O_WKD  + (long)WKD_PAD * HID)
#define O_WO   (O_WKU  + (long)KUP_N * KVLR)
#define O_QRN  (O_WO   + (long)HID * (HEADS * VD))
#define O_KVN  (O_QRN  + (long)S_LEN * QLR)
#define O_QALL (O_KVN  + (long)S_LEN * KVLR)
#define O_KALL (O_QALL + (long)HEADS * S_LEN * QD)
#define O_KV16 (O_KALL + (long)HEADS * S_LEN * QD)
#define O_ATTN (O_KV16 + (long)S_LEN * KUP_N)
#define O_CTX  (O_ATTN + (long)HEADS * S_LEN * S_LEN)
#define O_TOT  (O_CTX  + (long)S_LEN * HID)

__device__ __align__(256) float  g_f32[F_TOT];
__device__ __align__(256) __half g_h16[O_TOT];

// ---------------------------------------------------------------------------
__device__ __forceinline__ unsigned smem_u32(const void* p) {
    return (unsigned)__cvta_generic_to_shared(p);
}
__device__ __forceinline__ void ldm_x4(uint32_t r[4], unsigned addr) {
    asm volatile("ldmatrix.sync.aligned.m8n8.x4.shared.b16 {%0,%1,%2,%3}, [%4];"
                 : "=r"(r[0]), "=r"(r[1]), "=r"(r[2]), "=r"(r[3]) : "r"(addr));
}
__device__ __forceinline__ void ldm_x4t(uint32_t r[4], unsigned addr) {
    asm volatile("ldmatrix.sync.aligned.m8n8.x4.trans.shared.b16 {%0,%1,%2,%3}, [%4];"
                 : "=r"(r[0]), "=r"(r[1]), "=r"(r[2]), "=r"(r[3]) : "r"(addr));
}
__device__ __forceinline__ void mma16816(float d[4], const uint32_t a[4],
                                         const uint32_t b0, const uint32_t b1) {
    asm volatile(
        "mma.sync.aligned.m16n8k16.row.col.f32.f16.f16.f32 "
        "{%0,%1,%2,%3}, {%4,%5,%6,%7}, {%8,%9}, {%0,%1,%2,%3};"
        : "+f"(d[0]), "+f"(d[1]), "+f"(d[2]), "+f"(d[3])
        : "r"(a[0]), "r"(a[1]), "r"(a[2]), "r"(a[3]), "r"(b0), "r"(b1));
}
__device__ __forceinline__ void cp16(unsigned dst, const void* src) {
    asm volatile("cp.async.cg.shared.global [%0], [%1], 16;"
                 :: "r"(dst), "l"(src));
}
#define CP_COMMIT() asm volatile("cp.async.commit_group;" ::: "memory")
#define CP_WAIT1()  asm volatile("cp.async.wait_group 1;" ::: "memory")

// ---------------------------------------------------------------------------
__global__ void cvt_h(const float* __restrict__ x, __half* __restrict__ h,
                      long n)
{
    long i = ((long)blockIdx.x * 256 + threadIdx.x) * 4;
    if (i >= n) return;
    float4 v = *(const float4*)(x + i);
    __half2 a = __floats2half2_rn(v.x, v.y);
    __half2 b = __floats2half2_rn(v.z, v.w);
    uint2 u;
    u.x = *(uint32_t*)&a; u.y = *(uint32_t*)&b;
    *(uint2*)(h + i) = u;
}

// ---------------------------------------------------------------------------
// Tensor-core GEMM (mma.sync fp16), 256 threads, 8 warps (4m x 2n),
// warp tile 32x64, BM=BN=128, BK=32, 3-stage cp.async, 2 CTAs/SM.
//   BTRANS=0: C = scale*(A[M,K] @ B[N,K]^T)+bias
//   BTRANS=1: C = scale*(A[M,K] @ B[K,N])+bias   (ldmatrix.trans)
// CSKIP: skip blocks fully above the diagonal (QK; softmax writes zeros).
// CKLIM: K clamped to row0+128 (causal PV).
// SPLITK (PV only): col0=0, blockIdx.x = K-half. Rows < S/2: single block
//   (x=0) writes fp16 ctx directly. Rows >= S/2: x in {0,1} write fp32
//   partials to split[x]; combined by combine_ctx.
// ---------------------------------------------------------------------------
#define SST 40
#define BSTR 136
#define STG 3
#define B_OFF 10240u

template<bool CSKIP, bool CKLIM, bool BTRANS, bool SPLITK>
__global__ __launch_bounds__(256, 2)
void gemm_h(const __half* __restrict__ Ag, long sA,
            const __half* __restrict__ Bg, long sB,
            float* __restrict__ C, long sC,
            __half* __restrict__ Ch,
            int K, int lda, int ldb, int ldc, int Nvalid,
            const float* __restrict__ bias, float scale,
            float* __restrict__ split)
{
    constexpr unsigned STAGE = BTRANS ? (B_OFF + 32u * BSTR * 2u)   // 18944
                                      : (B_OFF + 128u * SST * 2u);  // 20480
    extern __shared__ __half sm[];

    const int bz = blockIdx.z;
    Ag += (long)bz * sA;
    Bg += (long)bz * sB;
    C  += (long)bz * sC;
    if (Ch) Ch += (long)bz * sC;

    const int row0 = blockIdx.y * 128;
    const int col0 = SPLITK ? 0 : blockIdx.x * 128;
    const int tid = threadIdx.x;

    if (CSKIP && col0 >= row0 + 128) return;

    int kStart = 0;
    int kEnd = CKLIM ? min(K, row0 + 128) : K;
    bool partial = false;
    if (SPLITK) {
        if (row0 < S_LEN / 2) {
            if (blockIdx.x) return;            // single block covers all K
        } else {
            partial = true;
            if (blockIdx.x == 0) kEnd = S_LEN / 2;
            else                 kStart = S_LEN / 2;
        }
    }
    const int nc = (kEnd - kStart) >> 5;

    const int wid = tid >> 5, lane = tid & 31;
    const int wm = wid & 3, wn = wid >> 2;

    // A global load: row tid/2, 32B chunk at (tid&1)*32B
    const int gr  = tid >> 1;
    const int gcb = (tid & 1) * 16;
    const __half* pA = Ag + (long)(row0 + gr) * lda + gcb;
    const unsigned smb  = smem_u32(sm);
    const unsigned aoff = (unsigned)(gr * SST + gcb) * 2;

    // B global load
    const __half* pB;
    unsigned boff;
    if (BTRANS) {
        const int br = tid >> 3;            // 0..31 (k rows)
        const int bc = (tid & 7) * 16;      // halves within 128-col row
        pB = Bg + (long)br * ldb + col0 + bc;
        boff = B_OFF + (unsigned)(br * BSTR + bc) * 2;
    } else {
        pB = Bg + (long)(col0 + gr) * ldb + gcb;
        boff = B_OFF + (unsigned)(gr * SST + gcb) * 2;
    }

    float acc[2][8][4];
#pragma unroll
    for (int i = 0; i < 2; i++)
#pragma unroll
        for (int j = 0; j < 8; j++)
#pragma unroll
            for (int k = 0; k < 4; k++) acc[i][j][k] = 0.f;

    auto load_stage = [&](int kc, int slot) {
        const int k0 = kStart + (kc << 5);
        const unsigned so = smb + (unsigned)slot * STAGE;
        cp16(so + aoff,      pA + k0);
        cp16(so + aoff + 16, pA + k0 + 8);
        if (BTRANS) {
            const __half* b = pB + (long)k0 * ldb;
            cp16(so + boff,      b);
            cp16(so + boff + 16, b + 8);
        } else {
            cp16(so + boff,      pB + k0);
            cp16(so + boff + 16, pB + k0 + 8);
        }
    };

    // prologue: stages 0..STG-2
#pragma unroll
    for (int s = 0; s < STG - 1; s++) {
        if (s < nc) load_stage(s, s);
        CP_COMMIT();
    }

    // per-thread ldmatrix offsets
    const int a_ri = lane & 15;
    const int a_k8 = (lane >> 4) << 3;
    const int b_ri = (lane & 7) + ((lane >> 4) << 3);
    const int b_k8 = ((lane >> 3) & 1) << 3;
    const int t_kr = lane & 15;
    const int t_n8 = ((lane >> 4) & 1) << 3;

    for (int c = 0; c < nc; ++c) {
        CP_WAIT1();
        __syncthreads();

        const unsigned so = smb + (unsigned)(c % STG) * STAGE;
#pragma unroll
        for (int kk = 0; kk < 2; kk++) {
            uint32_t af[2][4];
#pragma unroll
            for (int mi = 0; mi < 2; mi++) {
                unsigned ad = so +
                    (unsigned)((wm * 32 + mi * 16 + a_ri) * SST + kk * 16 + a_k8) * 2;
                ldm_x4(af[mi], ad);
            }
#pragma unroll
            for (int g = 0; g < 4; g++) {
                uint32_t bf[4];
                if (BTRANS) {
                    unsigned bd = so + B_OFF +
                        (unsigned)((kk * 16 + t_kr) * BSTR +
                                   wn * 64 + g * 16 + t_n8) * 2;
                    ldm_x4t(bf, bd);
                } else {
                    unsigned bd = so + B_OFF +
                        (unsigned)((wn * 64 + g * 16 + b_ri) * SST + kk * 16 + b_k8) * 2;
                    ldm_x4(bf, bd);
                }
#pragma unroll
                for (int mi = 0; mi < 2; mi++) {
                    mma16816(acc[mi][2*g],   af[mi], bf[0], bf[1]);
                    mma16816(acc[mi][2*g+1], af[mi], bf[2], bf[3]);
                }
            }
        }
        // prefetch stage c+STG-1 into the slot freed by iteration c-1
        const int nx = c + STG - 1;
        if (nx < nc) load_stage(nx, nx % STG);
        CP_COMMIT();
    }

    // epilogue
    float* dstP = nullptr;
    if (SPLITK)
        dstP = split + (long)blockIdx.x * S_LEN * HID + (long)bz * VD;
#pragma unroll
    for (int mi = 0; mi < 2; mi++) {
        const int rb = row0 + wm * 32 + mi * 16 + (lane >> 2);
#pragma unroll
        for (int f = 0; f < 8; f++) {
            const int cc = col0 + wn * 64 + f * 8 + ((lane & 3) << 1);
            if (cc >= Nvalid) continue;
            float b0 = 0.f, b1 = 0.f;
            if (bias) { b0 = bias[cc]; b1 = bias[cc + 1]; }
            float2 v0, v1;
            v0.x = acc[mi][f][0] * scale + b0;
            v0.y = acc[mi][f][1] * scale + b1;
            v1.x = acc[mi][f][2] * scale + b0;
            v1.y = acc[mi][f][3] * scale + b1;
            if (SPLITK && partial) {
                *(float2*)&dstP[(long)rb * ldc + cc]       = v0;
                *(float2*)&dstP[(long)(rb + 8) * ldc + cc] = v1;
                continue;
            }
            *(float2*)&C[(long)rb * ldc + cc]       = v0;
            *(float2*)&C[(long)(rb + 8) * ldc + cc] = v1;
            if (Ch) {
                __half2 h0 = __floats2half2_rn(v0.x, v0.y);
                __half2 h1 = __floats2half2_rn(v1.x, v1.y);
                *(uint32_t*)&Ch[(long)rb * ldc + cc]       = *(uint32_t*)&h0;
                *(uint32_t*)&Ch[(long)(rb + 8) * ldc + cc] = *(uint32_t*)&h1;
            }
        }
    }
}

// ---------------------------------------------------------------------------
// combine split-K partials for ctx rows [S/2, S): ctx16 = fp16(P0 + P1)
// ---------------------------------------------------------------------------
__global__ void combine_ctx(const float* __restrict__ P0,
                            const float* __restrict__ P1,
                            __half* __restrict__ ctx)
{
    const long base = (long)(S_LEN / 2) * HID;
    long i = ((long)blockIdx.x * 256 + threadIdx.x) * 4;
    float4 a = *(const float4*)(P0 + base + i);
    float4 b = *(const float4*)(P1 + base + i);
    __half2 h0 = __floats2half2_rn(a.x + b.x, a.y + b.y);
    __half2 h1 = __floats2half2_rn(a.z + b.z, a.w + b.w);
    uint2 u;
    u.x = *(uint32_t*)&h0; u.y = *(uint32_t*)&h1;
    *(uint2*)(ctx + base + i) = u;
}

// ---------------------------------------------------------------------------
__global__ void rmsnorm_h(const float* __restrict__ X,
                          const float* __restrict__ g,
                          __half* __restrict__ H, int n, int ldin)
{
    const float* x = X + (long)blockIdx.x * ldin;
    __half* h = H + (long)blockIdx.x * n;
    __shared__ float red[256];
    float s = 0.f;
    for (int i = threadIdx.x; i < n; i += 256) { float v = x[i]; s += v * v; }
    red[threadIdx.x] = s;
    __syncthreads();
    for (int o = 128; o > 0; o >>= 1) {
        if (threadIdx.x < o) red[threadIdx.x] += red[threadIdx.x + o];
        __syncthreads();
    }
    float r = rsqrtf(red[0] / (float)n + 1e-6f);
    for (int i = threadIdx.x; i < n; i += 256)
        h[i] = __float2half_rn(g[i] * x[i] * r);
}

// ---------------------------------------------------------------------------
__global__ void assemble_rope(const float* __restrict__ q,
                              const float* __restrict__ kvd,
                              const float* __restrict__ kv,
                              const int* __restrict__ pos_ids,
                              __half* __restrict__ qa,
                              __half* __restrict__ ka)
{
    const int s = blockIdx.x;
    const int t = threadIdx.x;
    __shared__ float cs[32], sn[32], kr[64];

    if (t < 32) {
        float pos = (float)pos_ids[s];
        double freq = exp(-log(10000.0) * (double)t / 32.0);
        float arg = pos * (float)freq;
        cs[t] = cosf(arg);
        sn[t] = sinf(arg);
    }
    __syncthreads();
    if (t < 32) {
        float x0 = kvd[(long)s * KVD_W + KVLR + 2 * t];
        float x1 = kvd[(long)s * KVD_W + KVLR + 2 * t + 1];
        kr[t]      = x0 * cs[t] - x1 * sn[t];
        kr[32 + t] = x1 * cs[t] + x0 * sn[t];
    }
    __syncthreads();

    for (int idx = t; idx < HEADS * QD; idx += 256) {
        int h = idx / QD, d = idx % QD;
        float qv, kvv;
        if (d < NOPE) {
            qv  = q[(long)s * QUP_N + h * QD + d];
            kvv = kv[(long)s * KUP_N + h * (NOPE + VD) + d];
        } else {
            int k = d - NOPE;
            int kk = k & 31;
            float x0 = q[(long)s * QUP_N + h * QD + NOPE + 2 * kk];
            float x1 = q[(long)s * QUP_N + h * QD + NOPE + 2 * kk + 1];
            qv = (k < 32) ? (x0 * cs[kk] - x1 * sn[kk])
                          : (x1 * cs[kk] + x0 * sn[kk]);
            kvv = kr[k];
        }
        long o = ((long)h * S_LEN + s) * QD + d;
        qa[o] = __float2half_rn(qv);
        ka[o] = __float2half_rn(kvv);
    }
}

// ---------------------------------------------------------------------------
// Causal softmax (exact R8): single DRAM read via smem staging. Writes fp32
// full row (normalized band + zero tail) and fp16 banded copy for PV.
// ---------------------------------------------------------------------------
__global__ void softmax_causal(float* __restrict__ attn,
                               __half* __restrict__ H)
{
    const long row = blockIdx.x;
    const int i = (int)(row & (S_LEN - 1));
    float* p = attn + row * S_LEN;
    __half* h = H + row * S_LEN;
    const int n = i + 1;
    const int band = ((i >> 7) + 1) << 7;
    __shared__ float srow[S_LEN];
    __shared__ float red[256];

    for (int j = threadIdx.x; j < n; j += 256) srow[j] = p[j];
    __syncthreads();

    float mx = -INFINITY;
    for (int j = threadIdx.x; j < n; j += 256) mx = fmaxf(mx, srow[j]);
    red[threadIdx.x] = mx;
    __syncthreads();
    for (int o = 128; o > 0; o >>= 1) {
        if (threadIdx.x < o)
            red[threadIdx.x] = fmaxf(red[threadIdx.x], red[threadIdx.x + o]);
        __syncthreads();
    }
    mx = red[0];
    __syncthreads();

    float s = 0.f;
    for (int j = threadIdx.x; j < n; j += 256) {
        float e = expf(srow[j] - mx);
        srow[j] = e;
        s += e;
    }
    red[threadIdx.x] = s;
    __syncthreads();
    for (int o = 128; o > 0; o >>= 1) {
        if (threadIdx.x < o) red[threadIdx.x] += red[threadIdx.x + o];
        __syncthreads();
    }
    float inv = 1.f / red[0];
    __syncthreads();

    for (int j = threadIdx.x; j < n; j += 256) {
        float v = srow[j] * inv;
        p[j] = v;
        h[j] = __float2half_rn(v);
    }
    __half z = __float2half_rn(0.f);
    for (int j = n + threadIdx.x; j < band; j += 256) h[j] = z;
    for (int j = n + threadIdx.x; j < S_LEN; j += 256) p[j] = 0.f;
}

// ---------------------------------------------------------------------------
extern "C" void kernel_launch(void* const* d_in, const int* in_sizes, int n_in,
                              void* d_out, int out_size)
{
    (void)in_sizes; (void)n_in; (void)out_size;
    const float* hid  = (const float*)d_in[0];
    const int*   pos  = (const int*)  d_in[1];
    const float* Wqd  = (const float*)d_in[3];
    const float* bqd  = (const float*)d_in[4];
    const float* gq   = (const float*)d_in[5];
    const float* Wqu  = (const float*)d_in[6];
    const float* Wkd  = (const float*)d_in[7];
    const float* bkd  = (const float*)d_in[8];
    const float* gkv  = (const float*)d_in[9];
    const float* Wku  = (const float*)d_in[10];
    const float* Wo   = (const float*)d_in[11];

    float* out  = (float*)d_out;
    float* attn = out + (long)S_LEN * HID;

    void *pf = nullptr, *ph = nullptr;
    cudaGetSymbolAddress(&pf, g_f32);
    cudaGetSymbolAddress(&ph, g_h16);
    float*  F = (float*)pf;
    __half* H = (__half*)ph;

    float* qraw = F + F_QRAW;
    float* qbuf = F + F_QBUF;
    float* kvd  = F + F_KVD;
    float* kv   = F + F_KV;
    float* ctx  = F + F_CTX;
    float* psk  = F + F_CT2;           // split-K partial base (2 buffers)

    const int SMEM_NT = STG * 20480;   // 61440
    const int SMEM_TR = STG * 18944;   // 56832
    static bool attr_done = false;
    if (!attr_done) {
        cudaFuncSetAttribute(gemm_h<false,false,false,false>,
            cudaFuncAttributeMaxDynamicSharedMemorySize, SMEM_NT);
        cudaFuncSetAttribute(gemm_h<true,false,false,false>,
            cudaFuncAttributeMaxDynamicSharedMemorySize, SMEM_NT);
        cudaFuncSetAttribute(gemm_h<false,true,true,true>,
            cudaFuncAttributeMaxDynamicSharedMemorySize, SMEM_TR);
        attr_done = true;
    }

    const dim3 blk(256);
    const float qk_scale = 0.07216878364870323f;   // 1/sqrt(192)

    // 0. convert inputs to fp16 (Wkd into 640-row padded region)
    cvt_h<<<(unsigned)(((long)S_LEN*HID+1023)/1024), blk>>>(hid, H+O_HID, (long)S_LEN*HID);
    cvt_h<<<(unsigned)(((long)QLR*HID+1023)/1024), blk>>>(Wqd, H+O_WQD, (long)QLR*HID);
    cvt_h<<<(unsigned)(((long)QUP_N*QLR+1023)/1024), blk>>>(Wqu, H+O_WQU, (long)QUP_N*QLR);
    cvt_h<<<(unsigned)(((long)KVD_W*HID+1023)/1024), blk>>>(Wkd, H+O_WKD, (long)KVD_W*HID);
    cvt_h<<<(unsigned)(((long)KUP_N*KVLR+1023)/1024), blk>>>(Wku, H+O_WKU, (long)KUP_N*KVLR);
    cvt_h<<<(unsigned)(((long)HID*HEADS*VD+1023)/1024), blk>>>(Wo, H+O_WO, (long)HID*HEADS*VD);

    // 1. qraw = hid @ Wq_down^T + bq
    gemm_h<false,false,false,false><<<dim3(QLR/128, S_LEN/128, 1), blk, SMEM_NT>>>(
        H+O_HID, 0, H+O_WQD, 0, qraw, 0, nullptr,
        HID, HID, HID, QLR, QLR, bqd, 1.f, nullptr);
    // 2. rmsnorm -> fp16
    rmsnorm_h<<<S_LEN, blk>>>(qraw, gq, H+O_QRN, QLR, QLR);
    // 3. q = qrn @ Wq_up^T
    gemm_h<false,false,false,false><<<dim3(QUP_N/128, S_LEN/128, 1), blk, SMEM_NT>>>(
        H+O_QRN, 0, H+O_WQU, 0, qbuf, 0, nullptr,
        QLR, QLR, QLR, QUP_N, QUP_N, nullptr, 1.f, nullptr);
    // 4. kvd = hid @ Wkv_down^T + bkv  (N=576 via 640-padded weights)
    gemm_h<false,false,false,false><<<dim3(WKD_PAD/128, S_LEN/128, 1), blk, SMEM_NT>>>(
        H+O_HID, 0, H+O_WKD, 0, kvd, 0, nullptr,
        HID, HID, HID, KVD_W, KVD_W, bkd, 1.f, nullptr);
    // 5. rmsnorm first 512 cols -> fp16
    rmsnorm_h<<<S_LEN, blk>>>(kvd, gkv, H+O_KVN, KVLR, KVD_W);
    // 6. kv = kvn @ Wkv_up^T ; epilogue emits fp16 kv16 copy for PV
    gemm_h<false,false,false,false><<<dim3(KUP_N/128, S_LEN/128, 1), blk, SMEM_NT>>>(
        H+O_KVN, 0, H+O_WKU, 0, kv, 0, H+O_KV16,
        KVLR, KVLR, KVLR, KUP_N, KUP_N, nullptr, 1.f, nullptr);
    // 7. assemble + rope -> fp16 qall/kall
    assemble_rope<<<S_LEN, blk>>>(qbuf, kvd, kv, pos, H+O_QALL, H+O_KALL);
    // 8. scores -> attn fp32 (causal block skip; softmax writes zero tail)
    gemm_h<true,false,false,false><<<dim3(S_LEN/128, S_LEN/128, HEADS), blk, SMEM_NT>>>(
        H+O_QALL, (long)S_LEN*QD, H+O_KALL, (long)S_LEN*QD,
        attn, (long)S_LEN*S_LEN, nullptr,
        QD, QD, QD, S_LEN, S_LEN, nullptr, qk_scale, nullptr);
    // 9. causal softmax -> fp32 full row + fp16 banded (single DRAM read)
    softmax_causal<<<HEADS * S_LEN, blk>>>(attn, H+O_ATTN);
    // 10. PV split-K: grid.x = K-half. Top rows: direct fp16 ctx (x=0 only).
    //     Bottom rows: fp32 partials to psk[0..1].
    gemm_h<false,true,true,true><<<dim3(2, S_LEN/128, HEADS), blk, SMEM_TR>>>(
        H+O_ATTN, (long)S_LEN*S_LEN,
        H+O_KV16 + NOPE, 256,
        ctx, (long)VD, H+O_CTX,
        S_LEN, S_LEN, KUP_N, HID, VD, nullptr, 1.f, psk);
    // 10b. combine bottom-half partials -> fp16 ctx
    combine_ctx<<<(S_LEN/2) * HID / 1024, blk>>>(psk, psk + (long)S_LEN*HID, H+O_CTX);
    // 11. out = ctx @ Wo^T
    gemm_h<false,false,false,false><<<dim3(HID/128, S_LEN/128, 1), blk, SMEM_NT>>>(
        H+O_CTX, 0, H+O_WO, 0, out, 0, nullptr,
        HID, HID, HID, HID, HID, nullptr, 1.f, nullptr);
}